// round 1
// baseline (speedup 1.0000x reference)
#include <cuda_runtime.h>

#define N_NODES 1024
#define D 64
#define ALPHA_F 0.2f
#define MASK_VAL_F -1000000000.0f
#define LN_EPS_F 1e-5f

// ---------------- scratch (no allocations allowed) ----------------
__device__ float g_Wh[N_NODES * D];
__device__ float g_ei[N_NODES * D];   // h @ E_i + edge_b (folded)
__device__ float g_ej[N_NODES * D];   // h @ E_j
__device__ float g_qi[N_NODES * D];   // Wh @ A_i + attn_b1 (folded)
__device__ float g_kj[N_NODES * D];   // Wh @ A_j
__device__ float g_e[N_NODES * N_NODES];

// ---------------- packed f32x2 helpers ----------------
__device__ __forceinline__ unsigned long long pack2(float a, float b) {
    unsigned long long r;
    asm("mov.b64 %0, {%1, %2};"
        : "=l"(r) : "r"(__float_as_uint(a)), "r"(__float_as_uint(b)));
    return r;
}
__device__ __forceinline__ void unpack2(unsigned long long v, float& a, float& b) {
    unsigned int x, y;
    asm("mov.b64 {%0, %1}, %2;" : "=r"(x), "=r"(y) : "l"(v));
    a = __uint_as_float(x);
    b = __uint_as_float(y);
}
__device__ __forceinline__ unsigned long long fma2(unsigned long long a,
                                                   unsigned long long b,
                                                   unsigned long long c) {
    unsigned long long d;
    asm("fma.rn.f32x2 %0, %1, %2, %3;" : "=l"(d) : "l"(a), "l"(b), "l"(c));
    return d;
}

__device__ __forceinline__ float warpReduceMax(float v) {
    #pragma unroll
    for (int o = 16; o > 0; o >>= 1) v = fmaxf(v, __shfl_xor_sync(0xffffffffu, v, o));
    return v;
}
__device__ __forceinline__ float warpReduceSum(float v) {
    #pragma unroll
    for (int o = 16; o > 0; o >>= 1) v += __shfl_xor_sync(0xffffffffu, v, o);
    return v;
}

// ================================================================
// Kernel 1: per-node projections.
//   Wh = h@W ; ei = h@E_i + edge_b ; ej = h@E_j
//   qi = Wh@A_i + attn_b1 ; kj = Wh@A_j
// 256 threads = 4 nodes x 64 dims
// ================================================================
__global__ void __launch_bounds__(256) prep_kernel(
    const float* __restrict__ h, const float* __restrict__ W,
    const float* __restrict__ attn_w1, const float* __restrict__ attn_b1,
    const float* __restrict__ edge_w, const float* __restrict__ edge_b)
{
    __shared__ float sh[4][64];
    __shared__ float swh[4][64];
    const int r = threadIdx.x >> 6;
    const int d = threadIdx.x & 63;
    const int n = blockIdx.x * 4 + r;

    sh[r][d] = h[n * D + d];
    __syncthreads();

    float wh = 0.f, ei = edge_b[d], ej = 0.f;
    #pragma unroll 8
    for (int k = 0; k < D; ++k) {
        const float hv = sh[r][k];
        wh += hv * W[k * D + d];
        ei += hv * edge_w[k * D + d];
        ej += hv * edge_w[(D + k) * D + d];
    }
    g_Wh[n * D + d] = wh;
    g_ei[n * D + d] = ei;
    g_ej[n * D + d] = ej;
    swh[r][d] = wh;
    __syncthreads();

    float qi = attn_b1[d], kj = 0.f;
    #pragma unroll 8
    for (int k = 0; k < D; ++k) {
        const float wv = swh[r][k];
        qi += wv * attn_w1[k * D + d];
        kj += wv * attn_w1[(D + k) * D + d];
    }
    g_qi[n * D + d] = qi;
    g_kj[n * D + d] = kj;
}

// ================================================================
// Kernel 2: attention scores for all (i,j).
//   t   = leaky(ei_i + ej_j)                    [folded edge_b]
//   pre = qi_i + kj_j + t @ A_e                 [folded attn_b1]
//   e   = leaky(pre) . w2 + b2 ;  mask by adj
// Block = 256 threads = 8 i x 32 j. A_e lives in SMEM (broadcast).
// 64 accumulators per thread packed into 32 f32x2 registers.
// ================================================================
__global__ void __launch_bounds__(256, 2) escore_kernel(
    const float* __restrict__ attn_w1, const float* __restrict__ attn_w2,
    const float* __restrict__ attn_b2, const int* __restrict__ adj)
{
    __shared__ unsigned long long sAe[64][32];  // A_e[k][d] as f32x2 pairs
    __shared__ float sEi[8][64];
    __shared__ float sQi[8][64];
    __shared__ float sEj[64][33];               // [k][j], padded
    __shared__ float sKj[64][33];               // [d][j], padded
    __shared__ float sW2[64];

    const int tid = threadIdx.x;
    const int i0 = blockIdx.y * 8;
    const int j0 = blockIdx.x * 32;

    // A_e = attn_w1 rows [128, 192)
    for (int x = tid; x < 64 * 32; x += 256) {
        const int k = x >> 5, d2 = x & 31;
        const float2 v = *((const float2*)(attn_w1 + (128 + k) * D) + d2);
        sAe[k][d2] = pack2(v.x, v.y);
    }
    for (int x = tid; x < 8 * 64; x += 256) {
        const int r = x >> 6, k = x & 63;
        sEi[r][k] = g_ei[(i0 + r) * D + k];
        sQi[r][k] = g_qi[(i0 + r) * D + k];
    }
    for (int x = tid; x < 32 * 64; x += 256) {
        const int c = x >> 6, k = x & 63;
        sEj[k][c] = g_ej[(j0 + c) * D + k];
        sKj[k][c] = g_kj[(j0 + c) * D + k];
    }
    if (tid < 64) sW2[tid] = attn_w2[tid];
    __syncthreads();

    const int ti = tid >> 5;   // i within tile (uniform per warp -> broadcast)
    const int tj = tid & 31;   // j within tile (lane -> conflict-free)

    unsigned long long acc[32];
    #pragma unroll
    for (int d2 = 0; d2 < 32; ++d2) {
        const float a = sQi[ti][2 * d2]     + sKj[2 * d2][tj];
        const float b = sQi[ti][2 * d2 + 1] + sKj[2 * d2 + 1][tj];
        acc[d2] = pack2(a, b);
    }

    #pragma unroll 2
    for (int k = 0; k < 64; ++k) {
        const float s = sEi[ti][k] + sEj[k][tj];
        const float t = fmaxf(s, ALPHA_F * s);        // leaky_relu, alpha<1
        const unsigned long long tt = pack2(t, t);
        #pragma unroll
        for (int d2 = 0; d2 < 32; ++d2)
            acc[d2] = fma2(tt, sAe[k][d2], acc[d2]);
    }

    float e = attn_b2[0];
    #pragma unroll
    for (int d2 = 0; d2 < 32; ++d2) {
        float lo, hi;
        unpack2(acc[d2], lo, hi);
        lo = fmaxf(lo, ALPHA_F * lo);
        hi = fmaxf(hi, ALPHA_F * hi);
        e += lo * sW2[2 * d2] + hi * sW2[2 * d2 + 1];
    }

    const int i = i0 + ti, j = j0 + tj;
    if (adj[i * N_NODES + j] == 0) e = MASK_VAL_F;
    g_e[i * N_NODES + j] = e;
}

// ================================================================
// Kernel 3: softmax over j, h' = attn @ Wh + h, layernorm. 1 block / row.
// ================================================================
__global__ void __launch_bounds__(256) softmax_ln_kernel(
    const float* __restrict__ h, const float* __restrict__ ln_g,
    const float* __restrict__ ln_b, float* __restrict__ out)
{
    __shared__ float sp[N_NODES];
    __shared__ float red[8];
    __shared__ float part[4][64];
    __shared__ float shp[64];
    __shared__ float s_stat, s_mu, s_var;

    const int i = blockIdx.x;
    const int t = threadIdx.x;
    const int lane = t & 31, wid = t >> 5;

    // max
    float m = -3.4e38f;
    for (int j = t; j < N_NODES; j += 256) {
        const float v = g_e[i * N_NODES + j];
        sp[j] = v;
        m = fmaxf(m, v);
    }
    m = warpReduceMax(m);
    if (lane == 0) red[wid] = m;
    __syncthreads();
    if (t == 0) {
        float mm = red[0];
        #pragma unroll
        for (int w = 1; w < 8; ++w) mm = fmaxf(mm, red[w]);
        s_stat = mm;
    }
    __syncthreads();
    m = s_stat;

    // exp + sum
    float s = 0.f;
    for (int j = t; j < N_NODES; j += 256) {
        const float p = __expf(sp[j] - m);
        sp[j] = p;
        s += p;
    }
    s = warpReduceSum(s);
    if (lane == 0) red[wid] = s;
    __syncthreads();
    if (t == 0) {
        float ss = 0.f;
        #pragma unroll
        for (int w = 0; w < 8; ++w) ss += red[w];
        s_stat = 1.0f / ss;
    }
    __syncthreads();
    const float inv = s_stat;

    // attn @ Wh : 4 j-groups x 64 dims
    const int g = t >> 6, d = t & 63;
    const int jb = g * 256;
    float a0 = 0.f, a1 = 0.f, a2 = 0.f, a3 = 0.f;
    #pragma unroll 4
    for (int jj = 0; jj < 256; jj += 4) {
        a0 += sp[jb + jj + 0] * g_Wh[(jb + jj + 0) * D + d];
        a1 += sp[jb + jj + 1] * g_Wh[(jb + jj + 1) * D + d];
        a2 += sp[jb + jj + 2] * g_Wh[(jb + jj + 2) * D + d];
        a3 += sp[jb + jj + 3] * g_Wh[(jb + jj + 3) * D + d];
    }
    part[g][d] = (a0 + a1) + (a2 + a3);
    __syncthreads();

    if (t < 64) {
        const float hp = (part[0][t] + part[1][t] + part[2][t] + part[3][t]) * inv
                         + h[i * D + t];
        shp[t] = hp;
    }
    __syncthreads();

    if (t < 32) {
        float v = shp[t] + shp[t + 32];
        v = warpReduceSum(v);
        if (t == 0) s_mu = v * (1.0f / 64.0f);
    }
    __syncthreads();
    if (t < 32) {
        const float mu = s_mu;
        const float d0 = shp[t] - mu, d1 = shp[t + 32] - mu;
        float v = d0 * d0 + d1 * d1;
        v = warpReduceSum(v);
        if (t == 0) s_var = v * (1.0f / 64.0f);
    }
    __syncthreads();
    if (t < 64) {
        const float mu = s_mu;
        const float rstd = rsqrtf(s_var + LN_EPS_F);
        out[i * D + t] = (shp[t] - mu) * rstd * ln_g[t] + ln_b[t];
    }
}

// ================================================================
extern "C" void kernel_launch(void* const* d_in, const int* in_sizes, int n_in,
                              void* d_out, int out_size) {
    const float* h        = (const float*)d_in[0];
    const int*   adj      = (const int*)  d_in[1];
    const float* W        = (const float*)d_in[2];
    const float* attn_w1  = (const float*)d_in[3];
    const float* attn_b1  = (const float*)d_in[4];
    const float* attn_w2  = (const float*)d_in[5];
    const float* attn_b2  = (const float*)d_in[6];
    const float* edge_w   = (const float*)d_in[7];
    const float* edge_b   = (const float*)d_in[8];
    const float* ln_g     = (const float*)d_in[9];
    const float* ln_b     = (const float*)d_in[10];
    float* out = (float*)d_out;

    prep_kernel<<<N_NODES / 4, 256>>>(h, W, attn_w1, attn_b1, edge_w, edge_b);

    dim3 grid(N_NODES / 32, N_NODES / 8);
    escore_kernel<<<grid, 256>>>(attn_w1, attn_w2, attn_b2, adj);

    softmax_ln_kernel<<<N_NODES, 256>>>(h, ln_g, ln_b, out);
}

// round 2
// speedup vs baseline: 1.3326x; 1.3326x over previous
#include <cuda_runtime.h>

#define N_NODES 1024
#define D 64
#define ALPHA_F 0.2f
#define MASK_VAL_F -1000000000.0f
#define LN_EPS_F 1e-5f

// ---------------- scratch (no allocations allowed) ----------------
__device__ float g_Wh[N_NODES * D];
__device__ float g_ei[N_NODES * D];   // h @ E_i + edge_b (folded)
__device__ float g_ej[N_NODES * D];   // h @ E_j
__device__ float g_qi[N_NODES * D];   // Wh @ A_i + attn_b1 (folded)
__device__ float g_kj[N_NODES * D];   // Wh @ A_j
__device__ float g_e[N_NODES * N_NODES];

// ---------------- packed f32x2 helpers ----------------
__device__ __forceinline__ unsigned long long pack2(float a, float b) {
    unsigned long long r;
    asm("mov.b64 %0, {%1, %2};"
        : "=l"(r) : "r"(__float_as_uint(a)), "r"(__float_as_uint(b)));
    return r;
}
__device__ __forceinline__ void unpack2(unsigned long long v, float& a, float& b) {
    unsigned int x, y;
    asm("mov.b64 {%0, %1}, %2;" : "=r"(x), "=r"(y) : "l"(v));
    a = __uint_as_float(x);
    b = __uint_as_float(y);
}
__device__ __forceinline__ unsigned long long fma2(unsigned long long a,
                                                   unsigned long long b,
                                                   unsigned long long c) {
    unsigned long long d;
    asm("fma.rn.f32x2 %0, %1, %2, %3;" : "=l"(d) : "l"(a), "l"(b), "l"(c));
    return d;
}

__device__ __forceinline__ float warpReduceMax(float v) {
    #pragma unroll
    for (int o = 16; o > 0; o >>= 1) v = fmaxf(v, __shfl_xor_sync(0xffffffffu, v, o));
    return v;
}
__device__ __forceinline__ float warpReduceSum(float v) {
    #pragma unroll
    for (int o = 16; o > 0; o >>= 1) v += __shfl_xor_sync(0xffffffffu, v, o);
    return v;
}

// ================================================================
// Kernel 1: per-node projections.
//   Wh = h@W ; ei = h@E_i + edge_b ; ej = h@E_j
//   qi = Wh@A_i + attn_b1 ; kj = Wh@A_j
// 256 threads = 4 nodes x 64 dims
// ================================================================
__global__ void __launch_bounds__(256) prep_kernel(
    const float* __restrict__ h, const float* __restrict__ W,
    const float* __restrict__ attn_w1, const float* __restrict__ attn_b1,
    const float* __restrict__ edge_w, const float* __restrict__ edge_b)
{
    __shared__ float sh[4][64];
    __shared__ float swh[4][64];
    const int r = threadIdx.x >> 6;
    const int d = threadIdx.x & 63;
    const int n = blockIdx.x * 4 + r;

    sh[r][d] = h[n * D + d];
    __syncthreads();

    float wh = 0.f, ei = edge_b[d], ej = 0.f;
    #pragma unroll 8
    for (int k = 0; k < D; ++k) {
        const float hv = sh[r][k];
        wh += hv * W[k * D + d];
        ei += hv * edge_w[k * D + d];
        ej += hv * edge_w[(D + k) * D + d];
    }
    g_Wh[n * D + d] = wh;
    g_ei[n * D + d] = ei;
    g_ej[n * D + d] = ej;
    swh[r][d] = wh;
    __syncthreads();

    float qi = attn_b1[d], kj = 0.f;
    #pragma unroll 8
    for (int k = 0; k < D; ++k) {
        const float wv = swh[r][k];
        qi += wv * attn_w1[k * D + d];
        kj += wv * attn_w1[(D + k) * D + d];
    }
    g_qi[n * D + d] = qi;
    g_kj[n * D + d] = kj;
}

// ================================================================
// Kernel 2: attention scores, GEMM-style register blocking.
//   Tile: 16 i x 16 j per block (256 pairs), full d=64.
//   Thread: 4 i-pairs x 16 d  => 32 f32x2 accumulators.
//   Per k: LDS.128 (4 ei) + LDS.32 (ej) + 8 LDS.64 (A_e) + 32 FFMA2.
// ================================================================
__global__ void __launch_bounds__(256, 2) escore_kernel(
    const float* __restrict__ attn_w1, const float* __restrict__ attn_w2,
    const float* __restrict__ attn_b2, const int* __restrict__ adj)
{
    __shared__ unsigned long long sAe[64][32];          // A_e[k][d2] f32x2
    __shared__ __align__(16) float sEiT[64][20];        // [k][i_local], pad 20
    __shared__ float sEjT[64][20];                      // [k][j_local]
    __shared__ float sQi[16][64];                       // [i_local][d]
    __shared__ float sKj[16][64];                       // [j_local][d]
    __shared__ float sW2[64];
    __shared__ float sPart[4][256];

    const int tid = threadIdx.x;
    const int i0 = blockIdx.y * 16;
    const int j0 = blockIdx.x * 16;

    // ---- stage tiles ----
    // A_e = attn_w1 rows [128, 192)
    for (int x = tid; x < 64 * 32; x += 256) {
        const int k = x >> 5, d2 = x & 31;
        const float2 v = *((const float2*)(attn_w1 + (128 + k) * D) + d2);
        sAe[k][d2] = pack2(v.x, v.y);
    }
    for (int x = tid; x < 16 * 64; x += 256) {
        const int il = x >> 6, k = x & 63;
        sEiT[k][il] = g_ei[(i0 + il) * D + k];
        sEjT[k][il] = g_ej[(j0 + il) * D + k];
        sQi[il][k]  = g_qi[(i0 + il) * D + k];
        sKj[il][k]  = g_kj[(j0 + il) * D + k];
    }
    if (tid < 64) sW2[tid] = attn_w2[tid];
    __syncthreads();

    const int td = tid >> 6;          // d-group 0..3 (uniform within warp)
    const int tp = tid & 63;          // pair-thread 0..63
    const int jl = tp & 15;           // local j
    const int ib = (tp >> 4) * 4;     // local i base (4 consecutive i)
    const int dg = td * 8;            // f32x2 column base (d2 index)

    // ---- init accumulators: qi[i,d] + kj[j,d] ----
    unsigned long long acc[4][8];
    #pragma unroll
    for (int p = 0; p < 4; ++p) {
        #pragma unroll
        for (int u = 0; u < 8; ++u) {
            const float2 q  = *(const float2*)&sQi[ib + p][2 * (dg + u)];
            const float2 kk = *(const float2*)&sKj[jl][2 * (dg + u)];
            acc[p][u] = pack2(q.x + kk.x, q.y + kk.y);
        }
    }

    // ---- main contraction over k ----
    #pragma unroll 4
    for (int k = 0; k < 64; ++k) {
        const float4 ei4 = *(const float4*)&sEiT[k][ib];
        const float  ejv = sEjT[k][jl];

        float t0 = ei4.x + ejv; t0 = fmaxf(t0, ALPHA_F * t0);
        float t1 = ei4.y + ejv; t1 = fmaxf(t1, ALPHA_F * t1);
        float t2 = ei4.z + ejv; t2 = fmaxf(t2, ALPHA_F * t2);
        float t3 = ei4.w + ejv; t3 = fmaxf(t3, ALPHA_F * t3);
        unsigned long long tt[4];
        tt[0] = pack2(t0, t0); tt[1] = pack2(t1, t1);
        tt[2] = pack2(t2, t2); tt[3] = pack2(t3, t3);

        unsigned long long ae[8];
        #pragma unroll
        for (int u = 0; u < 8; ++u) ae[u] = sAe[k][dg + u];

        #pragma unroll
        for (int p = 0; p < 4; ++p) {
            #pragma unroll
            for (int u = 0; u < 8; ++u)
                acc[p][u] = fma2(tt[p], ae[u], acc[p][u]);
        }
    }

    // ---- epilogue: leaky + dot with w2 chunk, partial per d-group ----
    #pragma unroll
    for (int p = 0; p < 4; ++p) {
        float s = 0.f;
        #pragma unroll
        for (int u = 0; u < 8; ++u) {
            float lo, hi;
            unpack2(acc[p][u], lo, hi);
            lo = fmaxf(lo, ALPHA_F * lo);
            hi = fmaxf(hi, ALPHA_F * hi);
            s += lo * sW2[2 * (dg + u)] + hi * sW2[2 * (dg + u) + 1];
        }
        sPart[td][tp * 4 + p] = s;
    }
    __syncthreads();

    // ---- reduce 4 d-groups, mask, store (one pair per thread) ----
    {
        const int q = tid;                       // pair index = tp*4 + p
        const int qtp = q >> 2, qp = q & 3;
        const int i = i0 + ((qtp >> 4) << 2) + qp;
        const int j = j0 + (qtp & 15);
        float e = sPart[0][q] + sPart[1][q] + sPart[2][q] + sPart[3][q]
                  + attn_b2[0];
        if (adj[i * N_NODES + j] == 0) e = MASK_VAL_F;
        g_e[i * N_NODES + j] = e;
    }
}

// ================================================================
// Kernel 3: softmax over j, h' = attn @ Wh + h, layernorm. 1 block / row.
// ================================================================
__global__ void __launch_bounds__(256) softmax_ln_kernel(
    const float* __restrict__ h, const float* __restrict__ ln_g,
    const float* __restrict__ ln_b, float* __restrict__ out)
{
    __shared__ float sp[N_NODES];
    __shared__ float red[8];
    __shared__ float part[4][64];
    __shared__ float shp[64];
    __shared__ float s_stat, s_mu, s_var;

    const int i = blockIdx.x;
    const int t = threadIdx.x;
    const int lane = t & 31, wid = t >> 5;

    // max
    float m = -3.4e38f;
    for (int j = t; j < N_NODES; j += 256) {
        const float v = g_e[i * N_NODES + j];
        sp[j] = v;
        m = fmaxf(m, v);
    }
    m = warpReduceMax(m);
    if (lane == 0) red[wid] = m;
    __syncthreads();
    if (t == 0) {
        float mm = red[0];
        #pragma unroll
        for (int w = 1; w < 8; ++w) mm = fmaxf(mm, red[w]);
        s_stat = mm;
    }
    __syncthreads();
    m = s_stat;

    // exp + sum
    float s = 0.f;
    for (int j = t; j < N_NODES; j += 256) {
        const float p = __expf(sp[j] - m);
        sp[j] = p;
        s += p;
    }
    s = warpReduceSum(s);
    if (lane == 0) red[wid] = s;
    __syncthreads();
    if (t == 0) {
        float ss = 0.f;
        #pragma unroll
        for (int w = 0; w < 8; ++w) ss += red[w];
        s_stat = 1.0f / ss;
    }
    __syncthreads();
    const float inv = s_stat;

    // attn @ Wh : 4 j-groups x 64 dims
    const int g = t >> 6, d = t & 63;
    const int jb = g * 256;
    float a0 = 0.f, a1 = 0.f, a2 = 0.f, a3 = 0.f;
    #pragma unroll 4
    for (int jj = 0; jj < 256; jj += 4) {
        a0 += sp[jb + jj + 0] * g_Wh[(jb + jj + 0) * D + d];
        a1 += sp[jb + jj + 1] * g_Wh[(jb + jj + 1) * D + d];
        a2 += sp[jb + jj + 2] * g_Wh[(jb + jj + 2) * D + d];
        a3 += sp[jb + jj + 3] * g_Wh[(jb + jj + 3) * D + d];
    }
    part[g][d] = (a0 + a1) + (a2 + a3);
    __syncthreads();

    if (t < 64) {
        const float hp = (part[0][t] + part[1][t] + part[2][t] + part[3][t]) * inv
                         + h[i * D + t];
        shp[t] = hp;
    }
    __syncthreads();

    if (t < 32) {
        float v = shp[t] + shp[t + 32];
        v = warpReduceSum(v);
        if (t == 0) s_mu = v * (1.0f / 64.0f);
    }
    __syncthreads();
    if (t < 32) {
        const float mu = s_mu;
        const float d0 = shp[t] - mu, d1 = shp[t + 32] - mu;
        float v = d0 * d0 + d1 * d1;
        v = warpReduceSum(v);
        if (t == 0) s_var = v * (1.0f / 64.0f);
    }
    __syncthreads();
    if (t < 64) {
        const float mu = s_mu;
        const float rstd = rsqrtf(s_var + LN_EPS_F);
        out[i * D + t] = (shp[t] - mu) * rstd * ln_g[t] + ln_b[t];
    }
}

// ================================================================
extern "C" void kernel_launch(void* const* d_in, const int* in_sizes, int n_in,
                              void* d_out, int out_size) {
    const float* h        = (const float*)d_in[0];
    const int*   adj      = (const int*)  d_in[1];
    const float* W        = (const float*)d_in[2];
    const float* attn_w1  = (const float*)d_in[3];
    const float* attn_b1  = (const float*)d_in[4];
    const float* attn_w2  = (const float*)d_in[5];
    const float* attn_b2  = (const float*)d_in[6];
    const float* edge_w   = (const float*)d_in[7];
    const float* edge_b   = (const float*)d_in[8];
    const float* ln_g     = (const float*)d_in[9];
    const float* ln_b     = (const float*)d_in[10];
    float* out = (float*)d_out;

    prep_kernel<<<N_NODES / 4, 256>>>(h, W, attn_w1, attn_b1, edge_w, edge_b);

    dim3 grid(N_NODES / 16, N_NODES / 16);
    escore_kernel<<<grid, 256>>>(attn_w1, attn_w2, attn_b2, adj);

    softmax_ln_kernel<<<N_NODES, 256>>>(h, ln_g, ln_b, out);
}

// round 4
// speedup vs baseline: 2.1752x; 1.6323x over previous
#include <cuda_runtime.h>
#include <cstdint>

#define N_NODES 1024
#define D 64
#define ALPHA_F 0.2f
#define MASK_VAL_F -1000000000.0f
#define LN_EPS_F 1e-5f

// ---------------- scratch (no allocations allowed) ----------------
__device__ float g_Wh[N_NODES * D];
__device__ float g_ei[N_NODES * D];   // h @ E_i + edge_b (folded)
__device__ float g_ej[N_NODES * D];   // h @ E_j
__device__ float g_qi[N_NODES * D];   // Wh @ A_i + attn_b1 (folded)
__device__ float g_kj[N_NODES * D];   // Wh @ A_j
__device__ float g_e[N_NODES * N_NODES];

// ---------------- helpers ----------------
__device__ __forceinline__ float warpReduceMax(float v) {
    #pragma unroll
    for (int o = 16; o > 0; o >>= 1) v = fmaxf(v, __shfl_xor_sync(0xffffffffu, v, o));
    return v;
}
__device__ __forceinline__ float warpReduceSum(float v) {
    #pragma unroll
    for (int o = 16; o > 0; o >>= 1) v += __shfl_xor_sync(0xffffffffu, v, o);
    return v;
}
__device__ __forceinline__ uint32_t f2tf32(float f) {
    uint32_t r;
    asm("cvt.rna.tf32.f32 %0, %1;" : "=r"(r) : "f"(f));
    return r;
}
__device__ __forceinline__ void mma_tf32_16x8x8(
    float& c0, float& c1, float& c2, float& c3,
    uint32_t a0, uint32_t a1, uint32_t a2, uint32_t a3,
    uint32_t b0, uint32_t b1)
{
    asm volatile(
        "mma.sync.aligned.m16n8k8.row.col.f32.tf32.tf32.f32 "
        "{%0,%1,%2,%3}, {%4,%5,%6,%7}, {%8,%9}, {%0,%1,%2,%3};"
        : "+f"(c0), "+f"(c1), "+f"(c2), "+f"(c3)
        : "r"(a0), "r"(a1), "r"(a2), "r"(a3), "r"(b0), "r"(b1));
}
__device__ __forceinline__ float leaky(float s) { return fmaxf(s, ALPHA_F * s); }

// ================================================================
// Kernel 1: per-node projections.
// ================================================================
__global__ void __launch_bounds__(256) prep_kernel(
    const float* __restrict__ h, const float* __restrict__ W,
    const float* __restrict__ attn_w1, const float* __restrict__ attn_b1,
    const float* __restrict__ edge_w, const float* __restrict__ edge_b)
{
    __shared__ float sh[4][64];
    __shared__ float swh[4][64];
    const int r = threadIdx.x >> 6;
    const int d = threadIdx.x & 63;
    const int n = blockIdx.x * 4 + r;

    sh[r][d] = h[n * D + d];
    __syncthreads();

    float wh = 0.f, ei = edge_b[d], ej = 0.f;
    #pragma unroll 8
    for (int k = 0; k < D; ++k) {
        const float hv = sh[r][k];
        wh += hv * W[k * D + d];
        ei += hv * edge_w[k * D + d];
        ej += hv * edge_w[(D + k) * D + d];
    }
    g_Wh[n * D + d] = wh;
    g_ei[n * D + d] = ei;
    g_ej[n * D + d] = ej;
    swh[r][d] = wh;
    __syncthreads();

    float qi = attn_b1[d], kj = 0.f;
    #pragma unroll 8
    for (int k = 0; k < D; ++k) {
        const float wv = swh[r][k];
        qi += wv * attn_w1[k * D + d];
        kj += wv * attn_w1[(D + k) * D + d];
    }
    g_qi[n * D + d] = qi;
    g_kj[n * D + d] = kj;
}

// ================================================================
// Kernel 2: attention scores via mma.sync tf32 (m16n8k8).
//   Per warp: 16 j x 64 d x 64 k per i.  B = A_e^T register-resident.
//   A frag built in registers: t = leaky(ei[i,k] + ej[j,k]).
//   acc initialized with qi[i,d]+kj[j,d]; epilogue leaky + dot w2.
// Block: 8 warps = 128 j; CHUNK_I=8 i's; grid (8, 128).
// ================================================================
#define CHUNK_I 8
#define PJ 68   // pad for sEj (conflict-free fragment loads)
#define PK 72   // pad for sKj
#define PA 68   // pad for sAe

__global__ void __launch_bounds__(256, 1) escore_hmma_kernel(
    const float* __restrict__ attn_w1, const float* __restrict__ attn_w2,
    const float* __restrict__ attn_b2, const int* __restrict__ adj)
{
    __shared__ float sEj[128][PJ];
    __shared__ float sKj[128][PK];
    __shared__ float sAe[64][PA];
    __shared__ float sEi[CHUNK_I][64];
    __shared__ float sQi[CHUNK_I][64];
    __shared__ float sW2[64];

    const int tid  = threadIdx.x;
    const int wid  = tid >> 5;
    const int lane = tid & 31;
    const int gid  = lane >> 2;     // 0..7
    const int tig  = lane & 3;      // 0..3
    const int j0   = blockIdx.x * 128;
    const int iBase = blockIdx.y * CHUNK_I;

    // ---- stage block tiles ----
    for (int x = tid; x < 128 * 64; x += 256) {
        const int j = x >> 6, k = x & 63;
        sEj[j][k] = g_ej[(j0 + j) * D + k];
        sKj[j][k] = g_kj[(j0 + j) * D + k];
    }
    for (int x = tid; x < 64 * 64; x += 256) {
        const int k = x >> 6, d = x & 63;
        sAe[k][d] = attn_w1[(128 + k) * D + d];   // A_e
    }
    for (int x = tid; x < CHUNK_I * 64; x += 256) {
        const int ii = x >> 6, d = x & 63;
        sEi[ii][d] = g_ei[(iBase + ii) * D + d];
        sQi[ii][d] = g_qi[(iBase + ii) * D + d];
    }
    if (tid < 64) sW2[tid] = attn_w2[tid];
    __syncthreads();

    // ---- B fragments (register-resident, whole kernel) ----
    // B[k][d] = A_e[k][d]; frag for (s, nt): b0=B[8s+tig][8nt+gid], b1=B[8s+tig+4][8nt+gid]
    uint32_t Bf[8][8][2];
    #pragma unroll
    for (int s = 0; s < 8; ++s)
        #pragma unroll
        for (int nt = 0; nt < 8; ++nt) {
            Bf[s][nt][0] = f2tf32(sAe[8 * s + tig][8 * nt + gid]);
            Bf[s][nt][1] = f2tf32(sAe[8 * s + tig + 4][8 * nt + gid]);
        }

    const int jw = wid * 16;
    const float b2 = attn_b2[0];

    #pragma unroll 1
    for (int ii = 0; ii < CHUNK_I; ++ii) {
        const int i = iBase + ii;

        // ei values this thread needs: eir[u] = ei[4u + tig]
        float eir[16];
        #pragma unroll
        for (int u = 0; u < 16; ++u) eir[u] = sEi[ii][4 * u + tig];

        // acc init = qi + kj (C-frag layout: c0=[gid][2tig], c1=+1, c2=[gid+8][2tig], c3=+1)
        float acc[8][4];
        #pragma unroll
        for (int nt = 0; nt < 8; ++nt) {
            const float2 q  = *(const float2*)&sQi[ii][8 * nt + 2 * tig];
            const float2 k0 = *(const float2*)&sKj[jw + gid][8 * nt + 2 * tig];
            const float2 k1 = *(const float2*)&sKj[jw + gid + 8][8 * nt + 2 * tig];
            acc[nt][0] = q.x + k0.x; acc[nt][1] = q.y + k0.y;
            acc[nt][2] = q.x + k1.x; acc[nt][3] = q.y + k1.y;
        }

        // k loop: 8 steps of k8
        #pragma unroll
        for (int s = 0; s < 8; ++s) {
            const float ej00 = sEj[jw + gid][8 * s + tig];
            const float ej10 = sEj[jw + gid + 8][8 * s + tig];
            const float ej01 = sEj[jw + gid][8 * s + tig + 4];
            const float ej11 = sEj[jw + gid + 8][8 * s + tig + 4];
            const uint32_t a0 = f2tf32(leaky(eir[2 * s]     + ej00));
            const uint32_t a1 = f2tf32(leaky(eir[2 * s]     + ej10));
            const uint32_t a2 = f2tf32(leaky(eir[2 * s + 1] + ej01));
            const uint32_t a3 = f2tf32(leaky(eir[2 * s + 1] + ej11));
            #pragma unroll
            for (int nt = 0; nt < 8; ++nt)
                mma_tf32_16x8x8(acc[nt][0], acc[nt][1], acc[nt][2], acc[nt][3],
                                a0, a1, a2, a3, Bf[s][nt][0], Bf[s][nt][1]);
        }

        // epilogue: leaky + dot w2, quad-reduce, mask, store
        float er0 = 0.f, er1 = 0.f;
        #pragma unroll
        for (int nt = 0; nt < 8; ++nt) {
            const float w0 = sW2[8 * nt + 2 * tig];
            const float w1 = sW2[8 * nt + 2 * tig + 1];
            er0 = fmaf(leaky(acc[nt][0]), w0, er0);
            er0 = fmaf(leaky(acc[nt][1]), w1, er0);
            er1 = fmaf(leaky(acc[nt][2]), w0, er1);
            er1 = fmaf(leaky(acc[nt][3]), w1, er1);
        }
        er0 += __shfl_xor_sync(0xffffffffu, er0, 1);
        er0 += __shfl_xor_sync(0xffffffffu, er0, 2);
        er1 += __shfl_xor_sync(0xffffffffu, er1, 1);
        er1 += __shfl_xor_sync(0xffffffffu, er1, 2);
        if (tig == 0) {
            const int jA = j0 + jw + gid;
            const int jB = jA + 8;
            float eA = er0 + b2, eB = er1 + b2;
            if (adj[i * N_NODES + jA] == 0) eA = MASK_VAL_F;
            if (adj[i * N_NODES + jB] == 0) eB = MASK_VAL_F;
            g_e[i * N_NODES + jA] = eA;
            g_e[i * N_NODES + jB] = eB;
        }
    }
}

// ================================================================
// Kernel 3: softmax + aggregate + LN; 4 rows per block (Wh reuse).
// ================================================================
#define R4 4
__global__ void __launch_bounds__(256) softmax_ln_kernel(
    const float* __restrict__ h, const float* __restrict__ ln_g,
    const float* __restrict__ ln_b, float* __restrict__ out)
{
    __shared__ float sp[R4][N_NODES];
    __shared__ float red[R4][8];
    __shared__ float part[R4][4][64];
    __shared__ float shp[R4][64];
    __shared__ float sInv[R4], sMu[R4], sVar[R4];

    const int i0 = blockIdx.x * R4;
    const int t = threadIdx.x;
    const int lane = t & 31, wid = t >> 5;

    float m[R4];
    #pragma unroll
    for (int r = 0; r < R4; ++r) m[r] = -3.4e38f;
    for (int j = t; j < N_NODES; j += 256) {
        #pragma unroll
        for (int r = 0; r < R4; ++r) {
            const float v = g_e[(i0 + r) * N_NODES + j];
            sp[r][j] = v;
            m[r] = fmaxf(m[r], v);
        }
    }
    #pragma unroll
    for (int r = 0; r < R4; ++r) {
        m[r] = warpReduceMax(m[r]);
        if (lane == 0) red[r][wid] = m[r];
    }
    __syncthreads();
    if (t < R4) {
        float mm = red[t][0];
        #pragma unroll
        for (int w = 1; w < 8; ++w) mm = fmaxf(mm, red[t][w]);
        sInv[t] = mm;
    }
    __syncthreads();
    #pragma unroll
    for (int r = 0; r < R4; ++r) m[r] = sInv[r];
    __syncthreads();

    float s[R4];
    #pragma unroll
    for (int r = 0; r < R4; ++r) s[r] = 0.f;
    for (int j = t; j < N_NODES; j += 256) {
        #pragma unroll
        for (int r = 0; r < R4; ++r) {
            const float p = __expf(sp[r][j] - m[r]);
            sp[r][j] = p;
            s[r] += p;
        }
    }
    #pragma unroll
    for (int r = 0; r < R4; ++r) {
        s[r] = warpReduceSum(s[r]);
        if (lane == 0) red[r][wid] = s[r];
    }
    __syncthreads();
    if (t < R4) {
        float ss = 0.f;
        #pragma unroll
        for (int w = 0; w < 8; ++w) ss += red[t][w];
        sInv[t] = 1.0f / ss;
    }
    __syncthreads();

    const int g = t >> 6, d = t & 63;
    const int jb = g * 256;
    float a[R4];
    #pragma unroll
    for (int r = 0; r < R4; ++r) a[r] = 0.f;
    #pragma unroll 2
    for (int jj = 0; jj < 256; ++jj) {
        const float whv = g_Wh[(jb + jj) * D + d];
        #pragma unroll
        for (int r = 0; r < R4; ++r) a[r] += sp[r][jb + jj] * whv;
    }
    #pragma unroll
    for (int r = 0; r < R4; ++r) part[r][g][d] = a[r];
    __syncthreads();

    {
        const int r = t >> 6, dd = t & 63;
        const float hp = (part[r][0][dd] + part[r][1][dd] + part[r][2][dd] + part[r][3][dd])
                         * sInv[r] + h[(i0 + r) * D + dd];
        shp[r][dd] = hp;
    }
    __syncthreads();
    if (t < 128) {
        const int r = t >> 5, l = t & 31;
        float v = shp[r][l] + shp[r][l + 32];
        v = warpReduceSum(v);
        if (l == 0) sMu[r] = v * (1.0f / 64.0f);
    }
    __syncthreads();
    if (t < 128) {
        const int r = t >> 5, l = t & 31;
        const float mu = sMu[r];
        const float d0 = shp[r][l] - mu, d1 = shp[r][l + 32] - mu;
        float v = d0 * d0 + d1 * d1;
        v = warpReduceSum(v);
        if (l == 0) sVar[r] = v * (1.0f / 64.0f);
    }
    __syncthreads();
    {
        const int r = t >> 6, dd = t & 63;
        const float mu = sMu[r];
        const float rstd = rsqrtf(sVar[r] + LN_EPS_F);
        out[(i0 + r) * D + dd] = (shp[r][dd] - mu) * rstd * ln_g[dd] + ln_b[dd];
    }
}

// ================================================================
extern "C" void kernel_launch(void* const* d_in, const int* in_sizes, int n_in,
                              void* d_out, int out_size) {
    const float* h        = (const float*)d_in[0];
    const int*   adj      = (const int*)  d_in[1];
    const float* W        = (const float*)d_in[2];
    const float* attn_w1  = (const float*)d_in[3];
    const float* attn_b1  = (const float*)d_in[4];
    const float* attn_w2  = (const float*)d_in[5];
    const float* attn_b2  = (const float*)d_in[6];
    const float* edge_w   = (const float*)d_in[7];
    const float* edge_b   = (const float*)d_in[8];
    const float* ln_g     = (const float*)d_in[9];
    const float* ln_b     = (const float*)d_in[10];
    float* out = (float*)d_out;

    prep_kernel<<<N_NODES / 4, 256>>>(h, W, attn_w1, attn_b1, edge_w, edge_b);

    dim3 grid(N_NODES / 128, N_NODES / CHUNK_I);
    escore_hmma_kernel<<<grid, 256>>>(attn_w1, attn_w2, attn_b2, adj);

    softmax_ln_kernel<<<N_NODES / R4, 256>>>(h, ln_g, ln_b, out);
}

// round 5
// speedup vs baseline: 2.9794x; 1.3697x over previous
#include <cuda_runtime.h>
#include <cstdint>

#define N_NODES 1024
#define D 64
#define ALPHA_F 0.2f
#define MASK_VAL_F -1000000000.0f
#define LN_EPS_F 1e-5f

// ---------------- scratch (no allocations allowed) ----------------
__device__ float g_Wh[N_NODES * D];
__device__ float g_ei[N_NODES * D];   // h @ E_i + edge_b (folded)
__device__ float g_ej[N_NODES * D];   // h @ E_j
__device__ float g_qi[N_NODES * D];   // Wh @ A_i + attn_b1 (folded)
__device__ float g_kj[N_NODES * D];   // Wh @ A_j
__device__ float g_e[N_NODES * N_NODES];

// ---------------- helpers ----------------
__device__ __forceinline__ float warpReduceMax(float v) {
    #pragma unroll
    for (int o = 16; o > 0; o >>= 1) v = fmaxf(v, __shfl_xor_sync(0xffffffffu, v, o));
    return v;
}
__device__ __forceinline__ float warpReduceSum(float v) {
    #pragma unroll
    for (int o = 16; o > 0; o >>= 1) v += __shfl_xor_sync(0xffffffffu, v, o);
    return v;
}
// pack {lo, hi} floats -> bf16x2 (element0 = lo)
__device__ __forceinline__ uint32_t pack_bf16x2(float lo, float hi) {
    uint32_t r;
    asm("cvt.rn.bf16x2.f32 %0, %1, %2;" : "=r"(r) : "f"(hi), "f"(lo));
    return r;
}
__device__ __forceinline__ void mma_bf16_16x8x16(
    float& c0, float& c1, float& c2, float& c3,
    uint32_t a0, uint32_t a1, uint32_t a2, uint32_t a3,
    uint32_t b0, uint32_t b1)
{
    asm volatile(
        "mma.sync.aligned.m16n8k16.row.col.f32.bf16.bf16.f32 "
        "{%0,%1,%2,%3}, {%4,%5,%6,%7}, {%8,%9}, {%0,%1,%2,%3};"
        : "+f"(c0), "+f"(c1), "+f"(c2), "+f"(c3)
        : "r"(a0), "r"(a1), "r"(a2), "r"(a3), "r"(b0), "r"(b1));
}
__device__ __forceinline__ float leaky(float s) { return fmaxf(s, ALPHA_F * s); }

// ================================================================
// Kernel 1: per-node projections. 128 blocks x 8 nodes, 2 nodes/thread.
// ================================================================
__global__ void __launch_bounds__(256) prep_kernel(
    const float* __restrict__ h, const float* __restrict__ W,
    const float* __restrict__ attn_w1, const float* __restrict__ attn_b1,
    const float* __restrict__ edge_w, const float* __restrict__ edge_b)
{
    __shared__ float sh[8][64];
    __shared__ float swh[8][64];
    const int t = threadIdx.x;
    const int d = t & 63;
    const int ng = t >> 6;               // 0..3 -> nodes ng*2, ng*2+1
    const int nb = blockIdx.x * 8;

    #pragma unroll
    for (int x = t; x < 8 * 64; x += 256)
        sh[x >> 6][x & 63] = h[nb * D + x];
    __syncthreads();

    const int n0 = ng * 2;
    float wh0 = 0.f, wh1 = 0.f;
    float ei0 = edge_b[d], ei1 = ei0;
    float ej0 = 0.f, ej1 = 0.f;
    #pragma unroll 8
    for (int k = 0; k < D; ++k) {
        const float w  = W[k * D + d];
        const float e1 = edge_w[k * D + d];
        const float e2 = edge_w[(D + k) * D + d];
        const float h0 = sh[n0][k], h1 = sh[n0 + 1][k];
        wh0 += h0 * w;  wh1 += h1 * w;
        ei0 += h0 * e1; ei1 += h1 * e1;
        ej0 += h0 * e2; ej1 += h1 * e2;
    }
    const int na = nb + n0;
    g_Wh[na * D + d] = wh0;       g_Wh[(na + 1) * D + d] = wh1;
    g_ei[na * D + d] = ei0;       g_ei[(na + 1) * D + d] = ei1;
    g_ej[na * D + d] = ej0;       g_ej[(na + 1) * D + d] = ej1;
    swh[n0][d] = wh0;             swh[n0 + 1][d] = wh1;
    __syncthreads();

    float qi0 = attn_b1[d], qi1 = qi0;
    float kj0 = 0.f, kj1 = 0.f;
    #pragma unroll 8
    for (int k = 0; k < D; ++k) {
        const float a1 = attn_w1[k * D + d];
        const float a2 = attn_w1[(D + k) * D + d];
        const float w0 = swh[n0][k], w1 = swh[n0 + 1][k];
        qi0 += w0 * a1; qi1 += w1 * a1;
        kj0 += w0 * a2; kj1 += w1 * a2;
    }
    g_qi[na * D + d] = qi0;       g_qi[(na + 1) * D + d] = qi1;
    g_kj[na * D + d] = kj0;       g_kj[(na + 1) * D + d] = kj1;
}

// ================================================================
// Kernel 2: attention scores via mma.sync bf16 (m16n8k16).
//   Per warp: 16 j x 64 d x 64 k per i.  B = A_e^T register-resident (bf16).
//   A frag built in registers: t = leaky(ei[i,k] + ej[j,k]) (fp32 add -> bf16).
//   acc initialized with qi[i,d]+kj[j,d] (fp32); epilogue leaky + dot w2 (fp32).
// Block: 8 warps = 128 j; CHUNK_I=16 i's; grid (8, 64).
// ================================================================
#define CHUNK_I 16
#define PJ 68
#define PK 72
#define PA 68

__global__ void __launch_bounds__(256, 1) escore_hmma_kernel(
    const float* __restrict__ attn_w1, const float* __restrict__ attn_w2,
    const float* __restrict__ attn_b2, const int* __restrict__ adj)
{
    __shared__ float sEj[128][PJ];
    __shared__ float sKj[128][PK];
    __shared__ float sAe[64][PA];
    __shared__ float sEi[CHUNK_I][64];
    __shared__ float sQi[CHUNK_I][64];
    __shared__ float sW2[64];

    const int tid  = threadIdx.x;
    const int wid  = tid >> 5;
    const int lane = tid & 31;
    const int gid  = lane >> 2;     // 0..7
    const int tig  = lane & 3;      // 0..3
    const int j0   = blockIdx.x * 128;
    const int iBase = blockIdx.y * CHUNK_I;

    // ---- stage block tiles ----
    for (int x = tid; x < 128 * 64; x += 256) {
        const int j = x >> 6, k = x & 63;
        sEj[j][k] = g_ej[(j0 + j) * D + k];
        sKj[j][k] = g_kj[(j0 + j) * D + k];
    }
    for (int x = tid; x < 64 * 64; x += 256) {
        const int k = x >> 6, d = x & 63;
        sAe[k][d] = attn_w1[(128 + k) * D + d];   // A_e
    }
    for (int x = tid; x < CHUNK_I * 64; x += 256) {
        const int ii = x >> 6, d = x & 63;
        sEi[ii][d] = g_ei[(iBase + ii) * D + d];
        sQi[ii][d] = g_qi[(iBase + ii) * D + d];
    }
    if (tid < 64) sW2[tid] = attn_w2[tid];
    __syncthreads();

    // ---- B fragments (bf16, register-resident, whole kernel) ----
    // step s covers k in [16s, 16s+16); b0 rows 2tig,2tig+1; b1 rows +8.
    uint32_t Bf[4][8][2];
    #pragma unroll
    for (int s = 0; s < 4; ++s)
        #pragma unroll
        for (int nt = 0; nt < 8; ++nt) {
            const int dd = 8 * nt + gid;
            const int kb = 16 * s + 2 * tig;
            Bf[s][nt][0] = pack_bf16x2(sAe[kb][dd],     sAe[kb + 1][dd]);
            Bf[s][nt][1] = pack_bf16x2(sAe[kb + 8][dd], sAe[kb + 9][dd]);
        }

    const int jw = wid * 16;
    const float b2 = attn_b2[0];

    #pragma unroll 1
    for (int ii = 0; ii < CHUNK_I; ++ii) {
        const int i = iBase + ii;

        // acc init = qi + kj
        float acc[8][4];
        #pragma unroll
        for (int nt = 0; nt < 8; ++nt) {
            const float2 q  = *(const float2*)&sQi[ii][8 * nt + 2 * tig];
            const float2 k0 = *(const float2*)&sKj[jw + gid][8 * nt + 2 * tig];
            const float2 k1 = *(const float2*)&sKj[jw + gid + 8][8 * nt + 2 * tig];
            acc[nt][0] = q.x + k0.x; acc[nt][1] = q.y + k0.y;
            acc[nt][2] = q.x + k1.x; acc[nt][3] = q.y + k1.y;
        }

        // k loop: 4 steps of k16
        #pragma unroll
        for (int s = 0; s < 4; ++s) {
            const int kb = 16 * s + 2 * tig;
            const float2 eia = *(const float2*)&sEi[ii][kb];
            const float2 eib = *(const float2*)&sEi[ii][kb + 8];
            const float2 ja0 = *(const float2*)&sEj[jw + gid][kb];
            const float2 jb0 = *(const float2*)&sEj[jw + gid][kb + 8];
            const float2 ja1 = *(const float2*)&sEj[jw + gid + 8][kb];
            const float2 jb1 = *(const float2*)&sEj[jw + gid + 8][kb + 8];

            const uint32_t a0 = pack_bf16x2(leaky(eia.x + ja0.x), leaky(eia.y + ja0.y));
            const uint32_t a1 = pack_bf16x2(leaky(eia.x + ja1.x), leaky(eia.y + ja1.y));
            const uint32_t a2 = pack_bf16x2(leaky(eib.x + jb0.x), leaky(eib.y + jb0.y));
            const uint32_t a3 = pack_bf16x2(leaky(eib.x + jb1.x), leaky(eib.y + jb1.y));

            #pragma unroll
            for (int nt = 0; nt < 8; ++nt)
                mma_bf16_16x8x16(acc[nt][0], acc[nt][1], acc[nt][2], acc[nt][3],
                                 a0, a1, a2, a3, Bf[s][nt][0], Bf[s][nt][1]);
        }

        // epilogue: leaky + dot w2, quad-reduce, mask, store
        float er0 = 0.f, er1 = 0.f;
        #pragma unroll
        for (int nt = 0; nt < 8; ++nt) {
            const float w0 = sW2[8 * nt + 2 * tig];
            const float w1 = sW2[8 * nt + 2 * tig + 1];
            er0 = fmaf(leaky(acc[nt][0]), w0, er0);
            er0 = fmaf(leaky(acc[nt][1]), w1, er0);
            er1 = fmaf(leaky(acc[nt][2]), w0, er1);
            er1 = fmaf(leaky(acc[nt][3]), w1, er1);
        }
        er0 += __shfl_xor_sync(0xffffffffu, er0, 1);
        er0 += __shfl_xor_sync(0xffffffffu, er0, 2);
        er1 += __shfl_xor_sync(0xffffffffu, er1, 1);
        er1 += __shfl_xor_sync(0xffffffffu, er1, 2);
        if (tig == 0) {
            const int jA = j0 + jw + gid;
            const int jB = jA + 8;
            float eA = er0 + b2, eB = er1 + b2;
            if (adj[i * N_NODES + jA] == 0) eA = MASK_VAL_F;
            if (adj[i * N_NODES + jB] == 0) eB = MASK_VAL_F;
            g_e[i * N_NODES + jA] = eA;
            g_e[i * N_NODES + jB] = eB;
        }
    }
}

// ================================================================
// Kernel 3: softmax + aggregate + LN; 8 rows per block (Wh reuse, 1 wave).
// ================================================================
#define R8 8
__global__ void __launch_bounds__(256) softmax_ln_kernel(
    const float* __restrict__ h, const float* __restrict__ ln_g,
    const float* __restrict__ ln_b, float* __restrict__ out)
{
    __shared__ float sp[R8][N_NODES];       // 32KB
    __shared__ float red[R8][8];
    __shared__ float part[R8][4][64];       // 8KB
    __shared__ float shp[R8][64];
    __shared__ float sInv[R8], sMu[R8], sVar[R8];

    const int i0 = blockIdx.x * R8;
    const int t = threadIdx.x;
    const int lane = t & 31, wid = t >> 5;

    // ---- max per row ----
    float m[R8];
    #pragma unroll
    for (int r = 0; r < R8; ++r) m[r] = -3.4e38f;
    for (int j = t; j < N_NODES; j += 256) {
        #pragma unroll
        for (int r = 0; r < R8; ++r) {
            const float v = g_e[(i0 + r) * N_NODES + j];
            sp[r][j] = v;
            m[r] = fmaxf(m[r], v);
        }
    }
    #pragma unroll
    for (int r = 0; r < R8; ++r) {
        m[r] = warpReduceMax(m[r]);
        if (lane == 0) red[r][wid] = m[r];
    }
    __syncthreads();
    if (t < R8) {
        float mm = red[t][0];
        #pragma unroll
        for (int w = 1; w < 8; ++w) mm = fmaxf(mm, red[t][w]);
        sInv[t] = mm;
    }
    __syncthreads();
    #pragma unroll
    for (int r = 0; r < R8; ++r) m[r] = sInv[r];
    __syncthreads();

    // ---- exp + sum ----
    float s[R8];
    #pragma unroll
    for (int r = 0; r < R8; ++r) s[r] = 0.f;
    for (int j = t; j < N_NODES; j += 256) {
        #pragma unroll
        for (int r = 0; r < R8; ++r) {
            const float p = __expf(sp[r][j] - m[r]);
            sp[r][j] = p;
            s[r] += p;
        }
    }
    #pragma unroll
    for (int r = 0; r < R8; ++r) {
        s[r] = warpReduceSum(s[r]);
        if (lane == 0) red[r][wid] = s[r];
    }
    __syncthreads();
    if (t < R8) {
        float ss = 0.f;
        #pragma unroll
        for (int w = 0; w < 8; ++w) ss += red[t][w];
        sInv[t] = 1.0f / ss;
    }
    __syncthreads();

    // ---- aggregate: 4 j-groups x 64 dims, 8 rows share Wh loads ----
    const int g = t >> 6, d = t & 63;
    const int jb = g * 256;
    float a[R8];
    #pragma unroll
    for (int r = 0; r < R8; ++r) a[r] = 0.f;
    #pragma unroll 2
    for (int jj = 0; jj < 256; jj += 4) {
        const float w0 = g_Wh[(jb + jj + 0) * D + d];
        const float w1 = g_Wh[(jb + jj + 1) * D + d];
        const float w2 = g_Wh[(jb + jj + 2) * D + d];
        const float w3 = g_Wh[(jb + jj + 3) * D + d];
        #pragma unroll
        for (int r = 0; r < R8; ++r) {
            const float4 p = *(const float4*)&sp[r][jb + jj];
            a[r] += p.x * w0 + p.y * w1 + p.z * w2 + p.w * w3;
        }
    }
    #pragma unroll
    for (int r = 0; r < R8; ++r) part[r][g][d] = a[r];
    __syncthreads();

    // ---- h' ----
    #pragma unroll
    for (int it = 0; it < 2; ++it) {
        const int idx = t + it * 256;
        const int r = idx >> 6, dd = idx & 63;
        const float hp = (part[r][0][dd] + part[r][1][dd] + part[r][2][dd] + part[r][3][dd])
                         * sInv[r] + h[(i0 + r) * D + dd];
        shp[r][dd] = hp;
    }
    __syncthreads();

    // ---- stats: warp w handles row w ----
    {
        const int r = wid;
        float v = shp[r][lane] + shp[r][lane + 32];
        v = warpReduceSum(v);
        if (lane == 0) sMu[r] = v * (1.0f / 64.0f);
    }
    __syncthreads();
    {
        const int r = wid;
        const float mu = sMu[r];
        const float d0 = shp[r][lane] - mu, d1 = shp[r][lane + 32] - mu;
        float v = d0 * d0 + d1 * d1;
        v = warpReduceSum(v);
        if (lane == 0) sVar[r] = v * (1.0f / 64.0f);
    }
    __syncthreads();

    // ---- normalize + write ----
    #pragma unroll
    for (int it = 0; it < 2; ++it) {
        const int idx = t + it * 256;
        const int r = idx >> 6, dd = idx & 63;
        const float mu = sMu[r];
        const float rstd = rsqrtf(sVar[r] + LN_EPS_F);
        out[(i0 + r) * D + dd] = (shp[r][dd] - mu) * rstd * ln_g[dd] + ln_b[dd];
    }
}

// ================================================================
extern "C" void kernel_launch(void* const* d_in, const int* in_sizes, int n_in,
                              void* d_out, int out_size) {
    const float* h        = (const float*)d_in[0];
    const int*   adj      = (const int*)  d_in[1];
    const float* W        = (const float*)d_in[2];
    const float* attn_w1  = (const float*)d_in[3];
    const float* attn_b1  = (const float*)d_in[4];
    const float* attn_w2  = (const float*)d_in[5];
    const float* attn_b2  = (const float*)d_in[6];
    const float* edge_w   = (const float*)d_in[7];
    const float* edge_b   = (const float*)d_in[8];
    const float* ln_g     = (const float*)d_in[9];
    const float* ln_b     = (const float*)d_in[10];
    float* out = (float*)d_out;

    prep_kernel<<<N_NODES / 8, 256>>>(h, W, attn_w1, attn_b1, edge_w, edge_b);

    dim3 grid(N_NODES / 128, N_NODES / CHUNK_I);
    escore_hmma_kernel<<<grid, 256>>>(attn_w1, attn_w2, attn_b2, adj);

    softmax_ln_kernel<<<N_NODES / R8, 256>>>(h, ln_g, ln_b, out);
}

// round 6
// speedup vs baseline: 3.2428x; 1.0884x over previous
#include <cuda_runtime.h>
#include <cstdint>

#define N_NODES 1024
#define D 64
#define ALPHA_F 0.2f
#define MASK_VAL_F -1000000000.0f
#define LN_EPS_F 1e-5f

// ---------------- scratch (no allocations allowed) ----------------
__device__ float g_Wh[N_NODES * D];
__device__ float g_ei[N_NODES * D];   // h @ E_i + edge_b (folded)
__device__ float g_ej[N_NODES * D];   // h @ E_j
__device__ float g_qi[N_NODES * D];   // Wh @ A_i + attn_b1 (folded)
__device__ float g_kj[N_NODES * D];   // Wh @ A_j
__device__ float g_e[N_NODES * N_NODES];

// ---------------- helpers ----------------
__device__ __forceinline__ float warpReduceMax(float v) {
    #pragma unroll
    for (int o = 16; o > 0; o >>= 1) v = fmaxf(v, __shfl_xor_sync(0xffffffffu, v, o));
    return v;
}
__device__ __forceinline__ float warpReduceSum(float v) {
    #pragma unroll
    for (int o = 16; o > 0; o >>= 1) v += __shfl_xor_sync(0xffffffffu, v, o);
    return v;
}
// pack {lo, hi} floats -> bf16x2 (element0 = lo)
__device__ __forceinline__ uint32_t pack_bf16x2(float lo, float hi) {
    uint32_t r;
    asm("cvt.rn.bf16x2.f32 %0, %1, %2;" : "=r"(r) : "f"(hi), "f"(lo));
    return r;
}
__device__ __forceinline__ void mma_bf16_16x8x16(
    float& c0, float& c1, float& c2, float& c3,
    uint32_t a0, uint32_t a1, uint32_t a2, uint32_t a3,
    uint32_t b0, uint32_t b1)
{
    asm volatile(
        "mma.sync.aligned.m16n8k16.row.col.f32.bf16.bf16.f32 "
        "{%0,%1,%2,%3}, {%4,%5,%6,%7}, {%8,%9}, {%0,%1,%2,%3};"
        : "+f"(c0), "+f"(c1), "+f"(c2), "+f"(c3)
        : "r"(a0), "r"(a1), "r"(a2), "r"(a3), "r"(b0), "r"(b1));
}
__device__ __forceinline__ float leaky(float s) { return fmaxf(s, ALPHA_F * s); }

// ================================================================
// Kernel 1: per-node projections. Weights staged in SMEM.
// 128 blocks x 8 nodes, 2 nodes/thread.
// ================================================================
__global__ void __launch_bounds__(256) prep_kernel(
    const float* __restrict__ h, const float* __restrict__ W,
    const float* __restrict__ attn_w1, const float* __restrict__ attn_b1,
    const float* __restrict__ edge_w, const float* __restrict__ edge_b)
{
    __shared__ float sWt[12288];          // 48KB: pass1 = W | E_i | E_j; pass2 = A_i | A_j
    __shared__ float sh[8][64];
    __shared__ float swh[8][64];
    const int t = threadIdx.x;
    const int d = t & 63;
    const int n0 = (t >> 6) * 2;
    const int nb = blockIdx.x * 8;

    // ---- stage pass-1 weights + h (float4) ----
    #pragma unroll
    for (int x = t; x < 1024; x += 256)
        ((float4*)sWt)[x] = ((const float4*)W)[x];
    #pragma unroll
    for (int x = t; x < 2048; x += 256)
        ((float4*)(sWt + 4096))[x] = ((const float4*)edge_w)[x];
    if (t < 128)
        ((float4*)sh)[t] = ((const float4*)(h + nb * D))[t];
    __syncthreads();

    float wh0 = 0.f, wh1 = 0.f;
    float ei0 = edge_b[d], ei1 = ei0;
    float ej0 = 0.f, ej1 = 0.f;
    #pragma unroll 8
    for (int k = 0; k < D; ++k) {
        const float w  = sWt[k * 64 + d];
        const float e1 = sWt[4096 + k * 64 + d];
        const float e2 = sWt[8192 + k * 64 + d];
        const float h0 = sh[n0][k], h1 = sh[n0 + 1][k];
        wh0 += h0 * w;  wh1 += h1 * w;
        ei0 += h0 * e1; ei1 += h1 * e1;
        ej0 += h0 * e2; ej1 += h1 * e2;
    }
    const int na = nb + n0;
    g_Wh[na * D + d] = wh0;       g_Wh[(na + 1) * D + d] = wh1;
    g_ei[na * D + d] = ei0;       g_ei[(na + 1) * D + d] = ei1;
    g_ej[na * D + d] = ej0;       g_ej[(na + 1) * D + d] = ej1;
    swh[n0][d] = wh0;             swh[n0 + 1][d] = wh1;
    __syncthreads();

    // ---- stage pass-2 weights: A_i | A_j = attn_w1 rows [0,128) ----
    #pragma unroll
    for (int x = t; x < 2048; x += 256)
        ((float4*)sWt)[x] = ((const float4*)attn_w1)[x];
    __syncthreads();

    float qi0 = attn_b1[d], qi1 = qi0;
    float kj0 = 0.f, kj1 = 0.f;
    #pragma unroll 8
    for (int k = 0; k < D; ++k) {
        const float a1 = sWt[k * 64 + d];
        const float a2 = sWt[4096 + k * 64 + d];
        const float w0 = swh[n0][k], w1 = swh[n0 + 1][k];
        qi0 += w0 * a1; qi1 += w1 * a1;
        kj0 += w0 * a2; kj1 += w1 * a2;
    }
    g_qi[na * D + d] = qi0;       g_qi[(na + 1) * D + d] = qi1;
    g_kj[na * D + d] = kj0;       g_kj[(na + 1) * D + d] = kj1;
}

// ================================================================
// Kernel 2: attention scores via mma.sync bf16 (m16n8k16).
//   Per warp: 16 j x 64 d x 64 k per i.  B = A_e^T register-resident (bf16).
//   2 blocks/SM for latency hiding (regs capped at 128).
// ================================================================
#define CHUNK_I 16
#define PJ 68
#define PK 68
#define PA 68

__global__ void __launch_bounds__(256, 2) escore_hmma_kernel(
    const float* __restrict__ attn_w1, const float* __restrict__ attn_w2,
    const float* __restrict__ attn_b2, const int* __restrict__ adj)
{
    __shared__ float sEj[128][PJ];
    __shared__ float sKj[128][PK];
    __shared__ float sAe[64][PA];
    __shared__ float sEi[CHUNK_I][64];
    __shared__ float sQi[CHUNK_I][64];
    __shared__ float sW2[64];

    const int tid  = threadIdx.x;
    const int wid  = tid >> 5;
    const int lane = tid & 31;
    const int gid  = lane >> 2;     // 0..7
    const int tig  = lane & 3;      // 0..3
    const int j0   = blockIdx.x * 128;
    const int iBase = blockIdx.y * CHUNK_I;

    // ---- stage block tiles ----
    for (int x = tid; x < 128 * 64; x += 256) {
        const int j = x >> 6, k = x & 63;
        sEj[j][k] = g_ej[(j0 + j) * D + k];
        sKj[j][k] = g_kj[(j0 + j) * D + k];
    }
    for (int x = tid; x < 64 * 64; x += 256) {
        const int k = x >> 6, d = x & 63;
        sAe[k][d] = attn_w1[(128 + k) * D + d];   // A_e
    }
    for (int x = tid; x < CHUNK_I * 64; x += 256) {
        const int ii = x >> 6, d = x & 63;
        sEi[ii][d] = g_ei[(iBase + ii) * D + d];
        sQi[ii][d] = g_qi[(iBase + ii) * D + d];
    }
    if (tid < 64) sW2[tid] = attn_w2[tid];
    __syncthreads();

    // ---- B fragments (bf16, register-resident, whole kernel) ----
    uint32_t Bf[4][8][2];
    #pragma unroll
    for (int s = 0; s < 4; ++s)
        #pragma unroll
        for (int nt = 0; nt < 8; ++nt) {
            const int dd = 8 * nt + gid;
            const int kb = 16 * s + 2 * tig;
            Bf[s][nt][0] = pack_bf16x2(sAe[kb][dd],     sAe[kb + 1][dd]);
            Bf[s][nt][1] = pack_bf16x2(sAe[kb + 8][dd], sAe[kb + 9][dd]);
        }

    const int jw = wid * 16;
    const float b2 = attn_b2[0];

    #pragma unroll 1
    for (int ii = 0; ii < CHUNK_I; ++ii) {
        const int i = iBase + ii;

        // acc init = qi + kj
        float acc[8][4];
        #pragma unroll
        for (int nt = 0; nt < 8; ++nt) {
            const float2 q  = *(const float2*)&sQi[ii][8 * nt + 2 * tig];
            const float2 k0 = *(const float2*)&sKj[jw + gid][8 * nt + 2 * tig];
            const float2 k1 = *(const float2*)&sKj[jw + gid + 8][8 * nt + 2 * tig];
            acc[nt][0] = q.x + k0.x; acc[nt][1] = q.y + k0.y;
            acc[nt][2] = q.x + k1.x; acc[nt][3] = q.y + k1.y;
        }

        // k loop: 4 steps of k16
        #pragma unroll
        for (int s = 0; s < 4; ++s) {
            const int kb = 16 * s + 2 * tig;
            const float2 eia = *(const float2*)&sEi[ii][kb];
            const float2 eib = *(const float2*)&sEi[ii][kb + 8];
            const float2 ja0 = *(const float2*)&sEj[jw + gid][kb];
            const float2 jb0 = *(const float2*)&sEj[jw + gid][kb + 8];
            const float2 ja1 = *(const float2*)&sEj[jw + gid + 8][kb];
            const float2 jb1 = *(const float2*)&sEj[jw + gid + 8][kb + 8];

            const uint32_t a0 = pack_bf16x2(leaky(eia.x + ja0.x), leaky(eia.y + ja0.y));
            const uint32_t a1 = pack_bf16x2(leaky(eia.x + ja1.x), leaky(eia.y + ja1.y));
            const uint32_t a2 = pack_bf16x2(leaky(eib.x + jb0.x), leaky(eib.y + jb0.y));
            const uint32_t a3 = pack_bf16x2(leaky(eib.x + jb1.x), leaky(eib.y + jb1.y));

            #pragma unroll
            for (int nt = 0; nt < 8; ++nt)
                mma_bf16_16x8x16(acc[nt][0], acc[nt][1], acc[nt][2], acc[nt][3],
                                 a0, a1, a2, a3, Bf[s][nt][0], Bf[s][nt][1]);
        }

        // epilogue: leaky + dot w2, quad-reduce, mask, store
        float er0 = 0.f, er1 = 0.f;
        #pragma unroll
        for (int nt = 0; nt < 8; ++nt) {
            const float w0 = sW2[8 * nt + 2 * tig];
            const float w1 = sW2[8 * nt + 2 * tig + 1];
            er0 = fmaf(leaky(acc[nt][0]), w0, er0);
            er0 = fmaf(leaky(acc[nt][1]), w1, er0);
            er1 = fmaf(leaky(acc[nt][2]), w0, er1);
            er1 = fmaf(leaky(acc[nt][3]), w1, er1);
        }
        er0 += __shfl_xor_sync(0xffffffffu, er0, 1);
        er0 += __shfl_xor_sync(0xffffffffu, er0, 2);
        er1 += __shfl_xor_sync(0xffffffffu, er1, 1);
        er1 += __shfl_xor_sync(0xffffffffu, er1, 2);
        if (tig == 0) {
            const int jA = j0 + jw + gid;
            const int jB = jA + 8;
            float eA = er0 + b2, eB = er1 + b2;
            if (adj[i * N_NODES + jA] == 0) eA = MASK_VAL_F;
            if (adj[i * N_NODES + jB] == 0) eB = MASK_VAL_F;
            g_e[i * N_NODES + jA] = eA;
            g_e[i * N_NODES + jB] = eB;
        }
    }
}

// ================================================================
// Kernel 3: softmax + aggregate + LN; 8 rows per block (Wh reuse, 1 wave).
// ================================================================
#define R8 8
__global__ void __launch_bounds__(256) softmax_ln_kernel(
    const float* __restrict__ h, const float* __restrict__ ln_g,
    const float* __restrict__ ln_b, float* __restrict__ out)
{
    __shared__ float sp[R8][N_NODES];       // 32KB
    __shared__ float red[R8][8];
    __shared__ float part[R8][4][64];       // 8KB
    __shared__ float shp[R8][64];
    __shared__ float sInv[R8], sMu[R8], sVar[R8];

    const int i0 = blockIdx.x * R8;
    const int t = threadIdx.x;
    const int lane = t & 31, wid = t >> 5;

    float m[R8];
    #pragma unroll
    for (int r = 0; r < R8; ++r) m[r] = -3.4e38f;
    for (int j = t; j < N_NODES; j += 256) {
        #pragma unroll
        for (int r = 0; r < R8; ++r) {
            const float v = g_e[(i0 + r) * N_NODES + j];
            sp[r][j] = v;
            m[r] = fmaxf(m[r], v);
        }
    }
    #pragma unroll
    for (int r = 0; r < R8; ++r) {
        m[r] = warpReduceMax(m[r]);
        if (lane == 0) red[r][wid] = m[r];
    }
    __syncthreads();
    if (t < R8) {
        float mm = red[t][0];
        #pragma unroll
        for (int w = 1; w < 8; ++w) mm = fmaxf(mm, red[t][w]);
        sInv[t] = mm;
    }
    __syncthreads();
    #pragma unroll
    for (int r = 0; r < R8; ++r) m[r] = sInv[r];
    __syncthreads();

    float s[R8];
    #pragma unroll
    for (int r = 0; r < R8; ++r) s[r] = 0.f;
    for (int j = t; j < N_NODES; j += 256) {
        #pragma unroll
        for (int r = 0; r < R8; ++r) {
            const float p = __expf(sp[r][j] - m[r]);
            sp[r][j] = p;
            s[r] += p;
        }
    }
    #pragma unroll
    for (int r = 0; r < R8; ++r) {
        s[r] = warpReduceSum(s[r]);
        if (lane == 0) red[r][wid] = s[r];
    }
    __syncthreads();
    if (t < R8) {
        float ss = 0.f;
        #pragma unroll
        for (int w = 0; w < 8; ++w) ss += red[t][w];
        sInv[t] = 1.0f / ss;
    }
    __syncthreads();

    const int g = t >> 6, d = t & 63;
    const int jb = g * 256;
    float a[R8];
    #pragma unroll
    for (int r = 0; r < R8; ++r) a[r] = 0.f;
    #pragma unroll 2
    for (int jj = 0; jj < 256; jj += 4) {
        const float w0 = g_Wh[(jb + jj + 0) * D + d];
        const float w1 = g_Wh[(jb + jj + 1) * D + d];
        const float w2 = g_Wh[(jb + jj + 2) * D + d];
        const float w3 = g_Wh[(jb + jj + 3) * D + d];
        #pragma unroll
        for (int r = 0; r < R8; ++r) {
            const float4 p = *(const float4*)&sp[r][jb + jj];
            a[r] += p.x * w0 + p.y * w1 + p.z * w2 + p.w * w3;
        }
    }
    #pragma unroll
    for (int r = 0; r < R8; ++r) part[r][g][d] = a[r];
    __syncthreads();

    #pragma unroll
    for (int it = 0; it < 2; ++it) {
        const int idx = t + it * 256;
        const int r = idx >> 6, dd = idx & 63;
        const float hp = (part[r][0][dd] + part[r][1][dd] + part[r][2][dd] + part[r][3][dd])
                         * sInv[r] + h[(i0 + r) * D + dd];
        shp[r][dd] = hp;
    }
    __syncthreads();

    {
        const int r = wid;
        float v = shp[r][lane] + shp[r][lane + 32];
        v = warpReduceSum(v);
        if (lane == 0) sMu[r] = v * (1.0f / 64.0f);
    }
    __syncthreads();
    {
        const int r = wid;
        const float mu = sMu[r];
        const float d0 = shp[r][lane] - mu, d1 = shp[r][lane + 32] - mu;
        float v = d0 * d0 + d1 * d1;
        v = warpReduceSum(v);
        if (lane == 0) sVar[r] = v * (1.0f / 64.0f);
    }
    __syncthreads();

    #pragma unroll
    for (int it = 0; it < 2; ++it) {
        const int idx = t + it * 256;
        const int r = idx >> 6, dd = idx & 63;
        const float mu = sMu[r];
        const float rstd = rsqrtf(sVar[r] + LN_EPS_F);
        out[(i0 + r) * D + dd] = (shp[r][dd] - mu) * rstd * ln_g[dd] + ln_b[dd];
    }
}

// ================================================================
extern "C" void kernel_launch(void* const* d_in, const int* in_sizes, int n_in,
                              void* d_out, int out_size) {
    const float* h        = (const float*)d_in[0];
    const int*   adj      = (const int*)  d_in[1];
    const float* W        = (const float*)d_in[2];
    const float* attn_w1  = (const float*)d_in[3];
    const float* attn_b1  = (const float*)d_in[4];
    const float* attn_w2  = (const float*)d_in[5];
    const float* attn_b2  = (const float*)d_in[6];
    const float* edge_w   = (const float*)d_in[7];
    const float* edge_b   = (const float*)d_in[8];
    const float* ln_g     = (const float*)d_in[9];
    const float* ln_b     = (const float*)d_in[10];
    float* out = (float*)d_out;

    prep_kernel<<<N_NODES / 8, 256>>>(h, W, attn_w1, attn_b1, edge_w, edge_b);

    dim3 grid(N_NODES / 128, N_NODES / CHUNK_I);
    escore_hmma_kernel<<<grid, 256>>>(attn_w1, attn_w2, attn_b2, adj);

    softmax_ln_kernel<<<N_NODES / R8, 256>>>(h, ln_g, ln_b, out);
}